// round 3
// baseline (speedup 1.0000x reference)
#include <cuda_runtime.h>
#include <math.h>

// Problem constants
#define B 4
#define C 64
#define NA 25
#define H 64
#define W 64
#define U 5
#define S 320        // H*U
#define NCHUNK 320   // C*U  (each chunk = 64 contiguous floats along w)
#define BSTRIDE 6553600  // C*NA*H*W
#define CSTRIDE 102400   // NA*H*W
#define NSTRIDE 4096     // H*W
#define SPLITK 8
#define KC_PER_SPLIT (NCHUNK / SPLITK)  // 40 chunks of 64 => 2560 elems per split

// Scratch (device globals; no allocations allowed)
__device__ float g_rq[B * S];
__device__ float g_rk[B * S];
__device__ float g_attp[(size_t)SPLITK * B * S * S];  // split-K partial scores
__device__ float g_att[(size_t)B * S * S];            // softmax probabilities

// Address of element (b, s, chunk ck, w=0) in the ORIGINAL (b,c,n,h,w) layout.
// s = h*5 + u ; d = c*320 + v*64 + w ; n = u*5 + v
__device__ __forceinline__ size_t elem_base(int b, int s, int ck) {
    int h = s / 5, uu = s - h * 5;
    int c = ck / 5, vv = ck - c * 5;
    return (size_t)b * BSTRIDE + (size_t)c * CSTRIDE + (size_t)(uu * 5 + vv) * NSTRIDE + (size_t)h * W;
}

// store a float4 into a 65-float-stride smem row (scalar STS: rows are only
// 4B aligned, STS.128 would fault)
__device__ __forceinline__ void sts4(float* p, float4 x) {
    p[0] = x.x; p[1] = x.y; p[2] = x.z; p[3] = x.w;
}

// ---------------------------------------------------------------------------
// K1: inverse L2 norms of each unfolded row (for Q and K).
// grid: (B*S, 2), block: 256
// ---------------------------------------------------------------------------
__global__ __launch_bounds__(256) void norms_kernel(const float* __restrict__ q,
                                                    const float* __restrict__ k) {
    int row = blockIdx.x;                    // 0..B*S-1
    const float* src = blockIdx.y ? k : q;
    float* dst = blockIdx.y ? g_rk : g_rq;
    int b = row / S, s = row - b * S;

    float acc = 0.f;
    // 320 chunks * 16 float4 each = 5120 float4 per row
    for (int i = threadIdx.x; i < NCHUNK * 16; i += 256) {
        int ck = i >> 4, f4 = i & 15;
        const float4 x = *(const float4*)(src + elem_base(b, s, ck) + f4 * 4);
        acc += x.x * x.x + x.y * x.y + x.z * x.z + x.w * x.w;
    }
    __shared__ float red[256];
    red[threadIdx.x] = acc;
    __syncthreads();
    for (int off = 128; off; off >>= 1) {
        if (threadIdx.x < off) red[threadIdx.x] += red[threadIdx.x + off];
        __syncthreads();
    }
    if (threadIdx.x == 0) dst[row] = 1.f / fmaxf(sqrtf(red[0]), 1e-12f);
}

// ---------------------------------------------------------------------------
// K2: scores = Q K^T over the causal lower-triangular 64x64 tile pairs.
// Split-K=8 into g_attp (no atomics -> deterministic).
// grid: (15 tile-pairs, SPLITK, B), block: 256 (16x16 threads, 4x4 micro-tile)
// ---------------------------------------------------------------------------
__global__ __launch_bounds__(256) void scores_kernel(const float* __restrict__ q,
                                                     const float* __restrict__ k) {
    __shared__ float Qs[64][65];
    __shared__ float Ks[64][65];
    int tp = blockIdx.x;
    int split = blockIdx.y;
    int b = blockIdx.z;
    // map tp -> (st, tt) with tt <= st
    int st = 0, r = tp;
    while (r > st) { r -= st + 1; st++; }
    int tt = r;
    int s0 = st * 64, t0 = tt * 64;

    int tid = threadIdx.x;
    int tx = tid & 15, ty = tid >> 4;
    float acc[4][4] = {};

    int ck_end = (split + 1) * KC_PER_SPLIT;
    for (int ck = split * KC_PER_SPLIT; ck < ck_end; ck++) {
        // cooperative load: 64 rows x 64 floats for both Q and K tiles
        #pragma unroll
        for (int f = tid; f < 1024; f += 256) {
            int rrow = f >> 4, c4 = f & 15;
            float4 xq = *(const float4*)(q + elem_base(b, s0 + rrow, ck) + c4 * 4);
            float4 xk = *(const float4*)(k + elem_base(b, t0 + rrow, ck) + c4 * 4);
            sts4(&Qs[rrow][c4 * 4], xq);
            sts4(&Ks[rrow][c4 * 4], xk);
        }
        __syncthreads();
        #pragma unroll 16
        for (int kk = 0; kk < 64; kk++) {
            float a[4], bb[4];
            #pragma unroll
            for (int i = 0; i < 4; i++) a[i] = Qs[ty * 4 + i][kk];
            #pragma unroll
            for (int j = 0; j < 4; j++) bb[j] = Ks[tx * 4 + j][kk];
            #pragma unroll
            for (int i = 0; i < 4; i++)
                #pragma unroll
                for (int j = 0; j < 4; j++)
                    acc[i][j] += a[i] * bb[j];
        }
        __syncthreads();
    }
    // epilogue: apply row/col inverse norms, store partial
    float* outp = g_attp + (size_t)split * (B * S * S);
    #pragma unroll
    for (int i = 0; i < 4; i++) {
        int s = s0 + ty * 4 + i;
        float rqv = g_rq[b * S + s];
        #pragma unroll
        for (int j = 0; j < 4; j++) {
            int t = t0 + tx * 4 + j;
            outp[((size_t)b * S + s) * S + t] = acc[i][j] * rqv * g_rk[b * S + t];
        }
    }
}

// ---------------------------------------------------------------------------
// K3: fused split-K reduce + causal softmax.
// grid: B*S rows, block: 320 threads (one per column t).
// Writes probabilities to g_att (zeros for t > s).
// ---------------------------------------------------------------------------
__global__ __launch_bounds__(S) void softmax_kernel() {
    int row = blockIdx.x;        // b*S + s
    int s = row % S;
    int tid = threadIdx.x;       // t
    __shared__ float red[10];

    float x;
    if (tid <= s) {
        x = 0.f;
        #pragma unroll
        for (int sp = 0; sp < SPLITK; sp++)
            x += g_attp[(size_t)sp * (B * S * S) + (size_t)row * S + tid];
    } else {
        x = -1e30f;
    }
    // block max
    float m = x;
    #pragma unroll
    for (int o = 16; o; o >>= 1) m = fmaxf(m, __shfl_xor_sync(0xffffffffu, m, o));
    if ((tid & 31) == 0) red[tid >> 5] = m;
    __syncthreads();
    float mall = red[0];
    #pragma unroll
    for (int i = 1; i < 10; i++) mall = fmaxf(mall, red[i]);

    float e = (tid <= s) ? expf(x - mall) : 0.f;
    float ssum = e;
    #pragma unroll
    for (int o = 16; o; o >>= 1) ssum += __shfl_xor_sync(0xffffffffu, ssum, o);
    __syncthreads();
    if ((tid & 31) == 0) red[tid >> 5] = ssum;
    __syncthreads();
    float tot = 0.f;
    #pragma unroll
    for (int i = 0; i < 10; i++) tot += red[i];

    g_att[(size_t)row * S + tid] = e / tot;
}

// ---------------------------------------------------------------------------
// K4: out = att @ V_unfold, fused fold + residual add + final store.
// grid: (320 d-chunks, 5 s-tiles, B), block: 256 (16x16, 4x4 micro-tile)
// Skips zero (above-causal) t tiles.
// ---------------------------------------------------------------------------
__global__ __launch_bounds__(256) void out_kernel(const float* __restrict__ v,
                                                  float* __restrict__ out) {
    __shared__ float Ps[64][65];
    __shared__ float Vs[64][65];
    int ck = blockIdx.x;
    int stile = blockIdx.y;
    int b = blockIdx.z;
    int s0 = stile * 64;
    int tid = threadIdx.x;
    int tx = tid & 15, ty = tid >> 4;
    float acc[4][4] = {};

    for (int tt = 0; tt <= stile; tt++) {
        int t0 = tt * 64;
        #pragma unroll
        for (int f = tid; f < 1024; f += 256) {
            int rrow = f >> 4, c4 = f & 15;
            float4 xp = *(const float4*)(g_att + ((size_t)b * S + s0 + rrow) * S + t0 + c4 * 4);
            float4 xv = *(const float4*)(v + elem_base(b, t0 + rrow, ck) + c4 * 4);
            sts4(&Ps[rrow][c4 * 4], xp);
            sts4(&Vs[rrow][c4 * 4], xv);
        }
        __syncthreads();
        #pragma unroll 16
        for (int kk = 0; kk < 64; kk++) {
            float a[4], bb[4];
            #pragma unroll
            for (int i = 0; i < 4; i++) a[i] = Ps[ty * 4 + i][kk];
            #pragma unroll
            for (int j = 0; j < 4; j++) bb[j] = Vs[kk][tx * 4 + j];
            #pragma unroll
            for (int i = 0; i < 4; i++)
                #pragma unroll
                for (int j = 0; j < 4; j++)
                    acc[i][j] += a[i] * bb[j];
        }
        __syncthreads();
    }
    // epilogue: residual add + write to original (b,c,n,h,w) layout
    #pragma unroll
    for (int i = 0; i < 4; i++) {
        size_t g = elem_base(b, s0 + ty * 4 + i, ck) + tx * 4;
        float4 vv = *(const float4*)(v + g);
        float4 o;
        o.x = acc[i][0] + vv.x;
        o.y = acc[i][1] + vv.y;
        o.z = acc[i][2] + vv.z;
        o.w = acc[i][3] + vv.w;
        *(float4*)(out + g) = o;
    }
}

// ---------------------------------------------------------------------------
extern "C" void kernel_launch(void* const* d_in, const int* in_sizes, int n_in,
                              void* d_out, int out_size) {
    const float* q = (const float*)d_in[0];
    const float* k = (const float*)d_in[1];
    const float* v = (const float*)d_in[2];
    float* out = (float*)d_out;

    norms_kernel<<<dim3(B * S, 2), 256>>>(q, k);
    scores_kernel<<<dim3(15, SPLITK, B), 256>>>(q, k);
    softmax_kernel<<<B * S, S>>>();
    out_kernel<<<dim3(NCHUNK, 5, B), 256>>>(v, out);
}

// round 4
// speedup vs baseline: 1.3066x; 1.3066x over previous
#include <cuda_runtime.h>
#include <math.h>

// Problem constants
#define B 4
#define C 64
#define NA 25
#define H 64
#define W 64
#define S 320        // H*U
#define NCHUNK 320   // C*U  (each chunk = 64 contiguous floats along w)
#define BSTRIDE 6553600  // C*NA*H*W
#define CSTRIDE 102400   // NA*H*W
#define NSTRIDE 4096     // H*W
#define SPLITK 8
#define KC_PER_SPLIT (NCHUNK / SPLITK)

#define QS_STRIDE 68     // k-major row stride (272B: 16B aligned, 4-way STS cap)

// Scratch (device globals; no allocations allowed)
__device__ float g_rq[B * S];
__device__ float g_rk[B * S];
__device__ float g_attp[(size_t)SPLITK * B * S * S];
__device__ float g_att[(size_t)B * S * S];

// Address of element (b, s, chunk ck, w=0) in the ORIGINAL (b,c,n,h,w) layout.
__device__ __forceinline__ size_t elem_base(int b, int s, int ck) {
    int h = s / 5, uu = s - h * 5;
    int c = ck / 5, vv = ck - c * 5;
    return (size_t)b * BSTRIDE + (size_t)c * CSTRIDE + (size_t)(uu * 5 + vv) * NSTRIDE + (size_t)h * W;
}

// Load-lane mapping: f in [0,1024): 8 lanes along k-quads (128B coalesced LDG),
// 4 consecutive rows per warp (caps STS transpose conflicts at 4-way).
__device__ __forceinline__ void lane_map(int f, int& c4, int& row) {
    c4 = (((f >> 9) & 1) << 3) | (f & 7);
    row = (f >> 3) & 63;
}

// ---------------------------------------------------------------------------
// K1: inverse L2 norms of each unfolded row (for Q and K).
// ---------------------------------------------------------------------------
__global__ __launch_bounds__(256) void norms_kernel(const float* __restrict__ q,
                                                    const float* __restrict__ k) {
    int row = blockIdx.x;
    const float* src = blockIdx.y ? k : q;
    float* dst = blockIdx.y ? g_rk : g_rq;
    int b = row / S, s = row - b * S;

    float acc = 0.f;
    for (int i = threadIdx.x; i < NCHUNK * 16; i += 256) {
        int ck = i >> 4, f4 = i & 15;
        const float4 x = *(const float4*)(src + elem_base(b, s, ck) + f4 * 4);
        acc += x.x * x.x + x.y * x.y + x.z * x.z + x.w * x.w;
    }
    __shared__ float red[256];
    red[threadIdx.x] = acc;
    __syncthreads();
    for (int off = 128; off; off >>= 1) {
        if (threadIdx.x < off) red[threadIdx.x] += red[threadIdx.x + off];
        __syncthreads();
    }
    if (threadIdx.x == 0) dst[row] = 1.f / fmaxf(sqrtf(red[0]), 1e-12f);
}

// ---------------------------------------------------------------------------
// K2: scores = Q K^T, causal 64x64 tile pairs, split-K=8.
// smem k-major: Qs[k][m] (stride 68, broadcast reads), Ks[k][n] (XOR-swizzled,
// conflict-free LDS.128 reads). Register prefetch pipeline.
// ---------------------------------------------------------------------------
__global__ __launch_bounds__(256) void scores_kernel(const float* __restrict__ q,
                                                     const float* __restrict__ k) {
    __shared__ float Qs[64 * QS_STRIDE];
    __shared__ float Ks[64 * 64];
    int tp = blockIdx.x, split = blockIdx.y, b = blockIdx.z;
    int st = 0, r = tp;
    while (r > st) { r -= st + 1; st++; }
    int tt = r;
    int s0 = st * 64, t0 = tt * 64;

    int tid = threadIdx.x;
    int tx = tid & 15, ty = tid >> 4;
    float acc[4][4] = {};

    float4 pq[4], pk[4];
    int ck = split * KC_PER_SPLIT;
    int ck_end = (split + 1) * KC_PER_SPLIT;
    #pragma unroll
    for (int j = 0; j < 4; j++) {
        int c4, row; lane_map(tid + 256 * j, c4, row);
        pq[j] = *(const float4*)(q + elem_base(b, s0 + row, ck) + c4 * 4);
        pk[j] = *(const float4*)(k + elem_base(b, t0 + row, ck) + c4 * 4);
    }

    for (; ck < ck_end; ck++) {
        __syncthreads();
        #pragma unroll
        for (int j = 0; j < 4; j++) {
            int c4, row; lane_map(tid + 256 * j, c4, row);
            int kb = c4 * 4;
            // Q: k-major scatter, stride 68
            Qs[(kb + 0) * QS_STRIDE + row] = pq[j].x;
            Qs[(kb + 1) * QS_STRIDE + row] = pq[j].y;
            Qs[(kb + 2) * QS_STRIDE + row] = pq[j].z;
            Qs[(kb + 3) * QS_STRIDE + row] = pq[j].w;
            // K: k-major + 16B-group XOR swizzle by (k&15)
            float kv[4] = {pk[j].x, pk[j].y, pk[j].z, pk[j].w};
            #pragma unroll
            for (int i = 0; i < 4; i++) {
                int kk2 = kb + i;
                Ks[kk2 * 64 + ((((row >> 2) ^ (kk2 & 15)) << 2) | (row & 3))] = kv[i];
            }
        }
        __syncthreads();
        if (ck + 1 < ck_end) {
            #pragma unroll
            for (int j = 0; j < 4; j++) {
                int c4, row; lane_map(tid + 256 * j, c4, row);
                pq[j] = *(const float4*)(q + elem_base(b, s0 + row, ck + 1) + c4 * 4);
                pk[j] = *(const float4*)(k + elem_base(b, t0 + row, ck + 1) + c4 * 4);
            }
        }
        #pragma unroll 16
        for (int kk = 0; kk < 64; kk++) {
            float4 a4 = *(const float4*)&Qs[kk * QS_STRIDE + ty * 4];
            float4 b4 = *(const float4*)&Ks[kk * 64 + ((tx ^ (kk & 15)) << 2)];
            acc[0][0] += a4.x * b4.x; acc[0][1] += a4.x * b4.y; acc[0][2] += a4.x * b4.z; acc[0][3] += a4.x * b4.w;
            acc[1][0] += a4.y * b4.x; acc[1][1] += a4.y * b4.y; acc[1][2] += a4.y * b4.z; acc[1][3] += a4.y * b4.w;
            acc[2][0] += a4.z * b4.x; acc[2][1] += a4.z * b4.y; acc[2][2] += a4.z * b4.z; acc[2][3] += a4.z * b4.w;
            acc[3][0] += a4.w * b4.x; acc[3][1] += a4.w * b4.y; acc[3][2] += a4.w * b4.z; acc[3][3] += a4.w * b4.w;
        }
    }
    float* outp = g_attp + (size_t)split * (B * S * S);
    #pragma unroll
    for (int i = 0; i < 4; i++) {
        int s = s0 + ty * 4 + i;
        float rqv = g_rq[b * S + s];
        #pragma unroll
        for (int j = 0; j < 4; j++) {
            int t = t0 + tx * 4 + j;
            outp[((size_t)b * S + s) * S + t] = acc[i][j] * rqv * g_rk[b * S + t];
        }
    }
}

// ---------------------------------------------------------------------------
// K3: fused split-K reduce + causal softmax. One 320-thread block per row.
// ---------------------------------------------------------------------------
__global__ __launch_bounds__(S) void softmax_kernel() {
    int row = blockIdx.x;
    int s = row % S;
    int tid = threadIdx.x;
    __shared__ float red[10];

    float x;
    if (tid <= s) {
        x = 0.f;
        #pragma unroll
        for (int sp = 0; sp < SPLITK; sp++)
            x += g_attp[(size_t)sp * (B * S * S) + (size_t)row * S + tid];
    } else {
        x = -1e30f;
    }
    float m = x;
    #pragma unroll
    for (int o = 16; o; o >>= 1) m = fmaxf(m, __shfl_xor_sync(0xffffffffu, m, o));
    if ((tid & 31) == 0) red[tid >> 5] = m;
    __syncthreads();
    float mall = red[0];
    #pragma unroll
    for (int i = 1; i < 10; i++) mall = fmaxf(mall, red[i]);

    float e = (tid <= s) ? expf(x - mall) : 0.f;
    float ssum = e;
    #pragma unroll
    for (int o = 16; o; o >>= 1) ssum += __shfl_xor_sync(0xffffffffu, ssum, o);
    __syncthreads();
    if ((tid & 31) == 0) red[tid >> 5] = ssum;
    __syncthreads();
    float tot = 0.f;
    #pragma unroll
    for (int i = 0; i < 10; i++) tot += red[i];

    g_att[(size_t)row * S + tid] = e / tot;
}

// ---------------------------------------------------------------------------
// K4: out = att @ V_unfold, fused fold + residual.
// smem: Ps[t][s] (k-major scatter, stride 68), Vs[t][w] natural (direct f4 STS).
// ---------------------------------------------------------------------------
__global__ __launch_bounds__(256) void out_kernel(const float* __restrict__ v,
                                                  float* __restrict__ out) {
    __shared__ float Ps[64 * QS_STRIDE];
    __shared__ float Vs[64 * 64];
    int ck = blockIdx.x, stile = blockIdx.y, b = blockIdx.z;
    int s0 = stile * 64;
    int tid = threadIdx.x;
    int tx = tid & 15, ty = tid >> 4;
    float acc[4][4] = {};

    float4 pp[4], pv[4];
    #pragma unroll
    for (int j = 0; j < 4; j++) {
        int c4, row; lane_map(tid + 256 * j, c4, row);
        pp[j] = *(const float4*)(g_att + ((size_t)b * S + s0 + row) * S + c4 * 4);
        pv[j] = *(const float4*)(v + elem_base(b, row, ck) + c4 * 4);
    }

    for (int tt = 0; tt <= stile; tt++) {
        __syncthreads();
        #pragma unroll
        for (int j = 0; j < 4; j++) {
            int c4, row; lane_map(tid + 256 * j, c4, row);
            int kb = c4 * 4;
            // att tile: k-major (k = t) scatter
            Ps[(kb + 0) * QS_STRIDE + row] = pp[j].x;
            Ps[(kb + 1) * QS_STRIDE + row] = pp[j].y;
            Ps[(kb + 2) * QS_STRIDE + row] = pp[j].z;
            Ps[(kb + 3) * QS_STRIDE + row] = pp[j].w;
            // V tile: already k-major (row = t, cols = w): direct vector store
            *(float4*)&Vs[row * 64 + c4 * 4] = pv[j];
        }
        __syncthreads();
        if (tt + 1 <= stile) {
            int t0n = (tt + 1) * 64;
            #pragma unroll
            for (int j = 0; j < 4; j++) {
                int c4, row; lane_map(tid + 256 * j, c4, row);
                pp[j] = *(const float4*)(g_att + ((size_t)b * S + s0 + row) * S + t0n + c4 * 4);
                pv[j] = *(const float4*)(v + elem_base(b, t0n + row, ck) + c4 * 4);
            }
        }
        #pragma unroll 16
        for (int kk = 0; kk < 64; kk++) {
            float4 a4 = *(const float4*)&Ps[kk * QS_STRIDE + ty * 4];
            float4 b4 = *(const float4*)&Vs[kk * 64 + tx * 4];
            acc[0][0] += a4.x * b4.x; acc[0][1] += a4.x * b4.y; acc[0][2] += a4.x * b4.z; acc[0][3] += a4.x * b4.w;
            acc[1][0] += a4.y * b4.x; acc[1][1] += a4.y * b4.y; acc[1][2] += a4.y * b4.z; acc[1][3] += a4.y * b4.w;
            acc[2][0] += a4.z * b4.x; acc[2][1] += a4.z * b4.y; acc[2][2] += a4.z * b4.z; acc[2][3] += a4.z * b4.w;
            acc[3][0] += a4.w * b4.x; acc[3][1] += a4.w * b4.y; acc[3][2] += a4.w * b4.z; acc[3][3] += a4.w * b4.w;
        }
    }
    #pragma unroll
    for (int i = 0; i < 4; i++) {
        size_t g = elem_base(b, s0 + ty * 4 + i, ck) + tx * 4;
        float4 vv = *(const float4*)(v + g);
        float4 o;
        o.x = acc[i][0] + vv.x;
        o.y = acc[i][1] + vv.y;
        o.z = acc[i][2] + vv.z;
        o.w = acc[i][3] + vv.w;
        *(float4*)(out + g) = o;
    }
}

// ---------------------------------------------------------------------------
extern "C" void kernel_launch(void* const* d_in, const int* in_sizes, int n_in,
                              void* d_out, int out_size) {
    const float* q = (const float*)d_in[0];
    const float* k = (const float*)d_in[1];
    const float* v = (const float*)d_in[2];
    float* out = (float*)d_out;

    norms_kernel<<<dim3(B * S, 2), 256>>>(q, k);
    scores_kernel<<<dim3(15, SPLITK, B), 256>>>(q, k);
    softmax_kernel<<<B * S, S>>>();
    out_kernel<<<dim3(NCHUNK, 5, B), 256>>>(v, out);
}

// round 5
// speedup vs baseline: 1.6279x; 1.2459x over previous
#include <cuda_runtime.h>
#include <math.h>

// Problem constants
#define B 4
#define C 64
#define NA 25
#define H 64
#define W 64
#define S 320        // H*U
#define NCHUNK 320   // C*U  (each chunk = 64 contiguous floats along w)
#define BSTRIDE 6553600  // C*NA*H*W
#define CSTRIDE 102400   // NA*H*W
#define NSTRIDE 4096     // H*W
#define SPLITK 8
#define KCS (NCHUNK / SPLITK)   // 40 chunks per split

typedef unsigned long long u64;

// Scratch (device globals; no allocations allowed)
__device__ float g_rq[B * S];
__device__ float g_rk[B * S];
__device__ float g_attp[(size_t)SPLITK * B * S * S];
__device__ float g_att[(size_t)B * S * S];

// Address of element (b, s, chunk ck, w=0) in the ORIGINAL (b,c,n,h,w) layout.
__device__ __forceinline__ size_t elem_base(int b, int s, int ck) {
    int h = s / 5, uu = s - h * 5;
    int c = ck / 5, vv = ck - c * 5;
    return (size_t)b * BSTRIDE + (size_t)c * CSTRIDE + (size_t)(uu * 5 + vv) * NSTRIDE + (size_t)h * W;
}

// ---- packed f32x2 helpers (FFMA2: only reachable via PTX) ----
__device__ __forceinline__ u64 pack2(float x) {
    u64 r; asm("mov.b64 %0, {%1, %1};" : "=l"(r) : "f"(x)); return r;
}
__device__ __forceinline__ void ffma2(u64& d, u64 a, u64 b) {
    asm("fma.rn.f32x2 %0, %1, %2, %0;" : "+l"(d) : "l"(a), "l"(b));
}
__device__ __forceinline__ float2 unpack2(u64 v) {
    float2 f; asm("mov.b64 {%0, %1}, %2;" : "=f"(f.x), "=f"(f.y) : "l"(v)); return f;
}

// Conflict-free k-major transpose scatter: element (k, col) stored at
// row k, column col ^ (4*((k>>2)&7)).  XOR touches bits 2-4 only, so 16B
// alignment of 4-float groups is preserved, and warp-wide scalar STS hits
// 32 distinct banks (rows in lane bits 0-1, k-quad in lane bits 2-4).
__device__ __forceinline__ void scatter4(float* sm, int c4, int col, float4 v, int stride) {
    int colx = col ^ ((c4 & 7) << 2);
    sm[(4 * c4 + 0) * stride + colx] = v.x;
    sm[(4 * c4 + 1) * stride + colx] = v.y;
    sm[(4 * c4 + 2) * stride + colx] = v.z;
    sm[(4 * c4 + 3) * stride + colx] = v.w;
}

// 16 packed FMAs of one k-step: a4 = 4 M-rows, (bl, bh) = 8 N-cols as f32x2.
#define KSTEP_FMA(a4, bl, bh, acc)                                                     \
    do {                                                                               \
        u64 ap_;                                                                       \
        ap_ = pack2((a4).x);                                                           \
        ffma2(acc[0][0], ap_, (bl).x); ffma2(acc[0][1], ap_, (bl).y);                  \
        ffma2(acc[0][2], ap_, (bh).x); ffma2(acc[0][3], ap_, (bh).y);                  \
        ap_ = pack2((a4).y);                                                           \
        ffma2(acc[1][0], ap_, (bl).x); ffma2(acc[1][1], ap_, (bl).y);                  \
        ffma2(acc[1][2], ap_, (bh).x); ffma2(acc[1][3], ap_, (bh).y);                  \
        ap_ = pack2((a4).z);                                                           \
        ffma2(acc[2][0], ap_, (bl).x); ffma2(acc[2][1], ap_, (bl).y);                  \
        ffma2(acc[2][2], ap_, (bh).x); ffma2(acc[2][3], ap_, (bh).y);                  \
        ap_ = pack2((a4).w);                                                           \
        ffma2(acc[3][0], ap_, (bl).x); ffma2(acc[3][1], ap_, (bl).y);                  \
        ffma2(acc[3][2], ap_, (bh).x); ffma2(acc[3][3], ap_, (bh).y);                  \
    } while (0)

// ---------------------------------------------------------------------------
// K1: inverse L2 norms of each unfolded row (for Q and K).
// ---------------------------------------------------------------------------
__global__ __launch_bounds__(256) void norms_kernel(const float* __restrict__ q,
                                                    const float* __restrict__ k) {
    int row = blockIdx.x;
    const float* src = blockIdx.y ? k : q;
    float* dst = blockIdx.y ? g_rk : g_rq;
    int b = row / S, s = row - b * S;

    float acc = 0.f;
    for (int i = threadIdx.x; i < NCHUNK * 16; i += 256) {
        int ck = i >> 4, f4 = i & 15;
        const float4 x = *(const float4*)(src + elem_base(b, s, ck) + f4 * 4);
        acc += x.x * x.x + x.y * x.y + x.z * x.z + x.w * x.w;
    }
    __shared__ float red[256];
    red[threadIdx.x] = acc;
    __syncthreads();
    for (int off = 128; off; off >>= 1) {
        if (threadIdx.x < off) red[threadIdx.x] += red[threadIdx.x + off];
        __syncthreads();
    }
    if (threadIdx.x == 0) dst[row] = 1.f / fmaxf(sqrtf(red[0]), 1e-12f);
}

// ---------------------------------------------------------------------------
// K2: scores = Q K^T.  Tile M=64 (s), N=128 (t), K-chunks of 64, split-K=8.
// 256 threads, micro 4x8 via FFMA2.  Causal tile list (9 pairs).
// ---------------------------------------------------------------------------
__global__ __launch_bounds__(256) void scores_kernel(const float* __restrict__ q,
                                                     const float* __restrict__ k) {
    __shared__ float As[64 * 64];    // [k][m], XOR-swizzled
    __shared__ float Bs[64 * 128];   // [k][n], XOR-swizzled
    const int MI[9] = {0, 1, 2, 2, 3, 3, 4, 4, 4};
    const int NJ[9] = {0, 0, 0, 1, 0, 1, 0, 1, 2};
    int pair = blockIdx.x, split = blockIdx.y, b = blockIdx.z;
    int s0 = MI[pair] * 64, t0 = NJ[pair] * 128;

    int tid = threadIdx.x;
    int tx = tid & 15, ty = tid >> 4;

    u64 acc[4][4];
    #pragma unroll
    for (int i = 0; i < 4; i++)
        #pragma unroll
        for (int j = 0; j < 4; j++) acc[i][j] = 0ull;

    float4 pa[4], pb[8];
    int ck = split * KCS;
    int ck_end = ck + KCS;

    // prefetch first chunk
    #pragma unroll
    for (int j = 0; j < 4; j++) {
        int idx = tid + 256 * j;
        int c4 = (idx & 7) | (((idx >> 9) & 1) << 3);
        int row = (idx >> 3) & 63;
        pa[j] = *(const float4*)(q + elem_base(b, s0 + row, ck) + c4 * 4);
    }
    #pragma unroll
    for (int j = 0; j < 8; j++) {
        int idx = tid + 256 * j;
        int c4 = (idx & 7) | ((idx >> 10) << 3);
        int t = t0 + ((idx >> 3) & 127);
        pb[j] = (t < S) ? *(const float4*)(k + elem_base(b, t, ck) + c4 * 4)
                        : make_float4(0.f, 0.f, 0.f, 0.f);
    }

    for (; ck < ck_end; ck++) {
        __syncthreads();
        #pragma unroll
        for (int j = 0; j < 4; j++) {
            int idx = tid + 256 * j;
            int c4 = (idx & 7) | (((idx >> 9) & 1) << 3);
            int row = (idx >> 3) & 63;
            scatter4(As, c4, row, pa[j], 64);
        }
        #pragma unroll
        for (int j = 0; j < 8; j++) {
            int idx = tid + 256 * j;
            int c4 = (idx & 7) | ((idx >> 10) << 3);
            int t = (idx >> 3) & 127;
            scatter4(Bs, c4, t, pb[j], 128);
        }
        __syncthreads();
        if (ck + 1 < ck_end) {
            #pragma unroll
            for (int j = 0; j < 4; j++) {
                int idx = tid + 256 * j;
                int c4 = (idx & 7) | (((idx >> 9) & 1) << 3);
                int row = (idx >> 3) & 63;
                pa[j] = *(const float4*)(q + elem_base(b, s0 + row, ck + 1) + c4 * 4);
            }
            #pragma unroll
            for (int j = 0; j < 8; j++) {
                int idx = tid + 256 * j;
                int c4 = (idx & 7) | ((idx >> 10) << 3);
                int t = t0 + ((idx >> 3) & 127);
                pb[j] = (t < S) ? *(const float4*)(k + elem_base(b, t, ck + 1) + c4 * 4)
                                : make_float4(0.f, 0.f, 0.f, 0.f);
            }
        }
        #pragma unroll 8
        for (int kk = 0; kk < 64; kk++) {
            int sw = ((kk >> 2) & 7) << 2;
            float4 a4 = *(const float4*)&As[kk * 64 + ((ty * 4) ^ sw)];
            const float* brow = &Bs[kk * 128 + ((tx * 4) ^ sw)];
            ulonglong2 bl = *(const ulonglong2*)brow;
            ulonglong2 bh = *(const ulonglong2*)(brow + 64);
            KSTEP_FMA(a4, bl, bh, acc);
        }
    }

    // epilogue: apply norms, store partials (f4 per quad, guard t<320)
    float rk0[8];
    #pragma unroll
    for (int h = 0; h < 2; h++)
        #pragma unroll
        for (int j = 0; j < 4; j++) {
            int t = t0 + h * 64 + tx * 4 + j;
            rk0[h * 4 + j] = (t < S) ? g_rk[b * S + t] : 0.f;
        }
    float* outp = g_attp + (size_t)split * (B * S * S);
    #pragma unroll
    for (int i = 0; i < 4; i++) {
        int s = s0 + ty * 4 + i;
        float rq = g_rq[b * S + s];
        #pragma unroll
        for (int h = 0; h < 2; h++) {
            int t = t0 + h * 64 + tx * 4;
            if (t < S) {
                float2 lo = unpack2(acc[i][2 * h]);
                float2 hi = unpack2(acc[i][2 * h + 1]);
                float4 o;
                o.x = lo.x * rq * rk0[h * 4 + 0];
                o.y = lo.y * rq * rk0[h * 4 + 1];
                o.z = hi.x * rq * rk0[h * 4 + 2];
                o.w = hi.y * rq * rk0[h * 4 + 3];
                *(float4*)&outp[((size_t)b * S + s) * S + t] = o;
            }
        }
    }
}

// ---------------------------------------------------------------------------
// K3: fused split-K reduce + causal softmax. One 320-thread block per row.
// ---------------------------------------------------------------------------
__global__ __launch_bounds__(S) void softmax_kernel() {
    int row = blockIdx.x;
    int s = row % S;
    int tid = threadIdx.x;
    __shared__ float red[10];

    float x;
    if (tid <= s) {
        x = 0.f;
        #pragma unroll
        for (int sp = 0; sp < SPLITK; sp++)
            x += g_attp[(size_t)sp * (B * S * S) + (size_t)row * S + tid];
    } else {
        x = -1e30f;
    }
    float m = x;
    #pragma unroll
    for (int o = 16; o; o >>= 1) m = fmaxf(m, __shfl_xor_sync(0xffffffffu, m, o));
    if ((tid & 31) == 0) red[tid >> 5] = m;
    __syncthreads();
    float mall = red[0];
    #pragma unroll
    for (int i = 1; i < 10; i++) mall = fmaxf(mall, red[i]);

    float e = (tid <= s) ? expf(x - mall) : 0.f;
    float ssum = e;
    #pragma unroll
    for (int o = 16; o; o >>= 1) ssum += __shfl_xor_sync(0xffffffffu, ssum, o);
    __syncthreads();
    if ((tid & 31) == 0) red[tid >> 5] = ssum;
    __syncthreads();
    float tot = 0.f;
    #pragma unroll
    for (int i = 0; i < 10; i++) tot += red[i];

    g_att[(size_t)row * S + tid] = e / tot;
}

// ---------------------------------------------------------------------------
// K4: out = att @ V_unfold + residual.  Tile M=64 (s), N=128 (2 w-chunks),
// K = t chunks of 64 (only stile+1 chunks: att is zero above the diagonal).
// grid: (160 chunk-pairs, 5 s-tiles, B), 256 threads, micro 4x8 FFMA2.
// ---------------------------------------------------------------------------
__global__ __launch_bounds__(256) void out_kernel(const float* __restrict__ v,
                                                  float* __restrict__ out) {
    __shared__ float As[64 * 64];    // att: [t][s], XOR-swizzled
    __shared__ float Vs[64 * 128];   // V:   [t][n], natural
    int ckp = blockIdx.x, stile = blockIdx.y, b = blockIdx.z;
    int s0 = stile * 64;
    int tid = threadIdx.x;
    int tx = tid & 15, ty = tid >> 4;

    u64 acc[4][4];
    #pragma unroll
    for (int i = 0; i < 4; i++)
        #pragma unroll
        for (int j = 0; j < 4; j++) acc[i][j] = 0ull;

    float4 pa[4], pv[8];
    // prefetch chunk tt=0
    #pragma unroll
    for (int j = 0; j < 4; j++) {
        int idx = tid + 256 * j;
        int c4 = (idx & 7) | (((idx >> 9) & 1) << 3);
        int row = (idx >> 3) & 63;
        pa[j] = *(const float4*)(g_att + ((size_t)b * S + s0 + row) * S + c4 * 4);
    }
    #pragma unroll
    for (int j = 0; j < 8; j++) {
        int c4n = (tid & 7) | ((j >> 1) << 3);
        int t = ((j & 1) << 5) | (tid >> 3);
        int ck = ckp * 2 + (c4n >> 4);
        pv[j] = *(const float4*)(v + elem_base(b, t, ck) + (c4n & 15) * 4);
    }

    for (int tt = 0; tt <= stile; tt++) {
        __syncthreads();
        #pragma unroll
        for (int j = 0; j < 4; j++) {
            int idx = tid + 256 * j;
            int c4 = (idx & 7) | (((idx >> 9) & 1) << 3);
            int row = (idx >> 3) & 63;
            scatter4(As, c4, row, pa[j], 64);
        }
        #pragma unroll
        for (int j = 0; j < 8; j++) {
            int c4n = (tid & 7) | ((j >> 1) << 3);
            int t = ((j & 1) << 5) | (tid >> 3);
            *(float4*)&Vs[t * 128 + c4n * 4] = pv[j];
        }
        __syncthreads();
        if (tt < stile) {
            int t0n = (tt + 1) * 64;
            #pragma unroll
            for (int j = 0; j < 4; j++) {
                int idx = tid + 256 * j;
                int c4 = (idx & 7) | (((idx >> 9) & 1) << 3);
                int row = (idx >> 3) & 63;
                pa[j] = *(const float4*)(g_att + ((size_t)b * S + s0 + row) * S + t0n + c4 * 4);
            }
            #pragma unroll
            for (int j = 0; j < 8; j++) {
                int c4n = (tid & 7) | ((j >> 1) << 3);
                int t = ((j & 1) << 5) | (tid >> 3);
                int ck = ckp * 2 + (c4n >> 4);
                pv[j] = *(const float4*)(v + elem_base(b, t0n + t, ck) + (c4n & 15) * 4);
            }
        }
        #pragma unroll 8
        for (int kk = 0; kk < 64; kk++) {
            int sw = ((kk >> 2) & 7) << 2;
            float4 a4 = *(const float4*)&As[kk * 64 + ((ty * 4) ^ sw)];
            const float* brow = &Vs[kk * 128 + tx * 4];
            ulonglong2 bl = *(const ulonglong2*)brow;
            ulonglong2 bh = *(const ulonglong2*)(brow + 64);
            KSTEP_FMA(a4, bl, bh, acc);
        }
    }

    // epilogue: residual add + store to original layout
    #pragma unroll
    for (int i = 0; i < 4; i++) {
        int s = s0 + ty * 4 + i;
        #pragma unroll
        for (int h = 0; h < 2; h++) {
            int ck = ckp * 2 + h;
            size_t g = elem_base(b, s, ck) + tx * 4;
            float4 vv = *(const float4*)(v + g);
            float2 lo = unpack2(acc[i][2 * h]);
            float2 hi = unpack2(acc[i][2 * h + 1]);
            float4 o;
            o.x = lo.x + vv.x;
            o.y = lo.y + vv.y;
            o.z = hi.x + vv.z;
            o.w = hi.y + vv.w;
            *(float4*)(out + g) = o;
        }
    }
}

// ---------------------------------------------------------------------------
extern "C" void kernel_launch(void* const* d_in, const int* in_sizes, int n_in,
                              void* d_out, int out_size) {
    const float* q = (const float*)d_in[0];
    const float* k = (const float*)d_in[1];
    const float* v = (const float*)d_in[2];
    float* out = (float*)d_out;

    norms_kernel<<<dim3(B * S, 2), 256>>>(q, k);
    scores_kernel<<<dim3(9, SPLITK, B), 256>>>(q, k);
    softmax_kernel<<<B * S, S>>>();
    out_kernel<<<dim3(160, 5, B), 256>>>(v, out);
}

// round 7
// speedup vs baseline: 3.7872x; 2.3264x over previous
#include <cuda_runtime.h>
#include <cuda_bf16.h>
#include <math.h>
#include <cstdint>

// Problem constants
#define B 4
#define C 64
#define NA 25
#define H 64
#define W 64
#define S 320        // H*U
#define NCHUNK 320   // chunks of 64 floats along w
#define D_TOT 20480  // feature dim
#define BSTRIDE 6553600
#define CSTRIDE 102400
#define NSTRIDE 4096
#define SK 16                       // split-K for scores
#define KSTEPS (D_TOT / SK / 64)    // 20 K-blocks of 64 per split

typedef unsigned long long u64;

// ---- scratch (device globals; no allocations allowed) ----
__device__ float g_rq[B * S];
__device__ float g_rk[B * S];
__device__ float g_attp[(size_t)SK * B * S * S];          // split-K partial scores (f32)
__device__ __nv_bfloat16 g_attb[(size_t)B * S * S];       // softmax probs (bf16)
__device__ __nv_bfloat16 g_qb[(size_t)B * S * D_TOT];
__device__ __nv_bfloat16 g_kb[(size_t)B * S * D_TOT];
__device__ __nv_bfloat16 g_vb[(size_t)B * S * D_TOT];

// original-layout address of (b, s, chunk ck, w=0)
__device__ __forceinline__ size_t elem_base(int b, int s, int ck) {
    int h = s / 5, uu = s - h * 5;
    int c = ck / 5, vv = ck - c * 5;
    return (size_t)b * BSTRIDE + (size_t)c * CSTRIDE + (size_t)(uu * 5 + vv) * NSTRIDE + (size_t)h * W;
}

// ---- PTX helpers (all sm_80-level: valid at target sm_103) ----
__device__ __forceinline__ uint32_t smem_u32(const void* p) {
    uint32_t a;
    asm("{ .reg .u64 t; cvta.to.shared.u64 t, %1; cvt.u32.u64 %0, t; }" : "=r"(a) : "l"(p));
    return a;
}
__device__ __forceinline__ void cpa16(uint32_t dst, const void* src) {
    asm volatile("{ .reg .u64 g; cvta.to.global.u64 g, %1; cp.async.cg.shared.global [%0], [g], 16; }"
                 :: "r"(dst), "l"(src) : "memory");
}
#define CP_COMMIT() asm volatile("cp.async.commit_group;" ::: "memory")
#define CP_WAIT0()  asm volatile("cp.async.wait_group 0;" ::: "memory")
#define CP_WAIT1()  asm volatile("cp.async.wait_group 1;" ::: "memory")

__device__ __forceinline__ void ldm4(uint32_t* r, uint32_t addr) {
    asm volatile("ldmatrix.sync.aligned.m8n8.x4.shared.b16 {%0,%1,%2,%3}, [%4];"
                 : "=r"(r[0]), "=r"(r[1]), "=r"(r[2]), "=r"(r[3]) : "r"(addr));
}
__device__ __forceinline__ void ldm4t(uint32_t* r, uint32_t addr) {
    asm volatile("ldmatrix.sync.aligned.m8n8.x4.trans.shared.b16 {%0,%1,%2,%3}, [%4];"
                 : "=r"(r[0]), "=r"(r[1]), "=r"(r[2]), "=r"(r[3]) : "r"(addr));
}
__device__ __forceinline__ void mma_bf16(float* d, const uint32_t* a, const uint32_t* b) {
    asm volatile("mma.sync.aligned.m16n8k16.row.col.f32.bf16.bf16.f32 "
                 "{%0,%1,%2,%3}, {%4,%5,%6,%7}, {%8,%9}, {%0,%1,%2,%3};"
                 : "+f"(d[0]), "+f"(d[1]), "+f"(d[2]), "+f"(d[3])
                 : "r"(a[0]), "r"(a[1]), "r"(a[2]), "r"(a[3]), "r"(b[0]), "r"(b[1]));
}

// ---------------------------------------------------------------------------
// K1: fused gather + bf16 convert (Q, K, V) + row inverse-norms (Q, K).
// grid (B*S, 3), 256 threads.
// ---------------------------------------------------------------------------
__global__ __launch_bounds__(256) void convnorm_kernel(const float* __restrict__ q,
                                                       const float* __restrict__ k,
                                                       const float* __restrict__ v) {
    int row = blockIdx.x;
    int which = blockIdx.y;
    const float* src = (which == 0) ? q : (which == 1) ? k : v;
    __nv_bfloat16* dstb = (which == 0) ? g_qb : (which == 1) ? g_kb : g_vb;
    int b = row / S, s = row - b * S;

    uint2* drow = (uint2*)(dstb + (size_t)row * D_TOT);
    float acc = 0.f;
    for (int i = threadIdx.x; i < NCHUNK * 16; i += 256) {
        int ck = i >> 4, f4 = i & 15;
        const float4 x = *(const float4*)(src + elem_base(b, s, ck) + f4 * 4);
        acc += x.x * x.x + x.y * x.y + x.z * x.z + x.w * x.w;
        __nv_bfloat162 p0 = __floats2bfloat162_rn(x.x, x.y);
        __nv_bfloat162 p1 = __floats2bfloat162_rn(x.z, x.w);
        uint2 wv;
        *reinterpret_cast<__nv_bfloat162*>(&wv.x) = p0;
        *reinterpret_cast<__nv_bfloat162*>(&wv.y) = p1;
        drow[i] = wv;
    }
    if (which < 2) {
        __shared__ float red[256];
        red[threadIdx.x] = acc;
        __syncthreads();
        for (int off = 128; off; off >>= 1) {
            if (threadIdx.x < off) red[threadIdx.x] += red[threadIdx.x + off];
            __syncthreads();
        }
        if (threadIdx.x == 0)
            (which ? g_rk : g_rq)[row] = 1.f / fmaxf(sqrtf(red[0]), 1e-12f);
    }
}

// ---------------------------------------------------------------------------
// K2: scores = Q K^T via mma.sync bf16.  Tile 128x128, K-blocks of 64,
// split-K=16.  cp.async double buffer, XOR-swizzled smem, causal tile list.
// grid (6 pairs, 16 splits, B), 256 threads, 64KB dynamic smem.
// ---------------------------------------------------------------------------
#define SC_A0 0
#define SC_A1 16384
#define SC_B0 32768
#define SC_B1 49152
#define SC_SMEM 65536

__global__ __launch_bounds__(256) void scores_mma() {
    extern __shared__ char sm[];
    uint32_t sb = smem_u32(sm);
    const int MI[6] = {0, 1, 1, 2, 2, 2};
    const int NJ[6] = {0, 0, 1, 0, 1, 2};
    int pair = blockIdx.x, split = blockIdx.y, b = blockIdx.z;
    int s0 = MI[pair] * 128, t0 = NJ[pair] * 128;
    int tid = threadIdx.x, l = tid & 31, wid = tid >> 5;
    int wm = wid >> 2, wn = wid & 3;    // warp grid 2 (M) x 4 (N)
    int d_base = split * (D_TOT / SK);

    const __nv_bfloat16* qrow = g_qb + (size_t)b * S * D_TOT;
    const __nv_bfloat16* krow = g_kb + (size_t)b * S * D_TOT;

    float acc[4][4][4];
    #pragma unroll
    for (int f = 0; f < 4; f++)
        #pragma unroll
        for (int nf = 0; nf < 4; nf++)
            #pragma unroll
            for (int e = 0; e < 4; e++) acc[f][nf][e] = 0.f;

    const uint32_t AOF[2] = {SC_A0, SC_A1}, BOF[2] = {SC_B0, SC_B1};

    // fill step 0
    {
        int d0 = d_base;
        #pragma unroll
        for (int j = 0; j < 4; j++) {
            int idx = tid + 256 * j, r = idx >> 3, g = idx & 7;
            int s = s0 + r; if (s >= S) s = S - 1;
            cpa16(sb + SC_A0 + r * 128 + ((g ^ (r & 7)) << 4), qrow + (size_t)s * D_TOT + d0 + g * 8);
        }
        #pragma unroll
        for (int j = 0; j < 4; j++) {
            int idx = tid + 256 * j, r = idx >> 3, g = idx & 7;
            int t = t0 + r; if (t >= S) t = S - 1;
            cpa16(sb + SC_B0 + r * 128 + ((g ^ (r & 7)) << 4), krow + (size_t)t * D_TOT + d0 + g * 8);
        }
        CP_COMMIT();
    }

    for (int step = 0; step < KSTEPS; step++) {
        int buf = step & 1;
        if (step + 1 < KSTEPS) {
            int d0 = d_base + (step + 1) * 64;
            uint32_t a_of = AOF[buf ^ 1], b_of = BOF[buf ^ 1];
            #pragma unroll
            for (int j = 0; j < 4; j++) {
                int idx = tid + 256 * j, r = idx >> 3, g = idx & 7;
                int s = s0 + r; if (s >= S) s = S - 1;
                cpa16(sb + a_of + r * 128 + ((g ^ (r & 7)) << 4), qrow + (size_t)s * D_TOT + d0 + g * 8);
            }
            #pragma unroll
            for (int j = 0; j < 4; j++) {
                int idx = tid + 256 * j, r = idx >> 3, g = idx & 7;
                int t = t0 + r; if (t >= S) t = S - 1;
                cpa16(sb + b_of + r * 128 + ((g ^ (r & 7)) << 4), krow + (size_t)t * D_TOT + d0 + g * 8);
            }
            CP_COMMIT();
            CP_WAIT1();
        } else {
            CP_WAIT0();
        }
        __syncthreads();
        uint32_t Ab = sb + AOF[buf], Bb = sb + BOF[buf];
        #pragma unroll
        for (int kk = 0; kk < 4; kk++) {
            uint32_t af[4][4], bfr[2][4];
            #pragma unroll
            for (int f = 0; f < 4; f++) {
                int rowA = wm * 64 + f * 16 + (l & 15);
                int g = 2 * kk + (l >> 4);
                ldm4(af[f], Ab + rowA * 128 + ((g ^ (l & 7)) << 4));
            }
            #pragma unroll
            for (int h = 0; h < 2; h++) {
                int rowB = wn * 32 + h * 16 + (l & 7) + ((l >> 4) << 3);
                int g = 2 * kk + ((l >> 3) & 1);
                ldm4(bfr[h], Bb + rowB * 128 + ((g ^ (rowB & 7)) << 4));
            }
            #pragma unroll
            for (int f = 0; f < 4; f++)
                #pragma unroll
                for (int nf = 0; nf < 4; nf++)
                    mma_bf16(acc[f][nf], af[f], &bfr[nf >> 1][(nf & 1) * 2]);
        }
        __syncthreads();
    }

    // epilogue: apply rq*rk, store split partials
    float* outp = g_attp + (size_t)split * (B * S * S) + (size_t)b * S * S;
    #pragma unroll
    for (int f = 0; f < 4; f++) {
        int r0 = s0 + wm * 64 + f * 16 + (l >> 2);
        #pragma unroll
        for (int half = 0; half < 2; half++) {
            int s = r0 + half * 8;
            if (s < S) {
                float rq = __ldg(&g_rq[b * S + s]);
                #pragma unroll
                for (int nf = 0; nf < 4; nf++) {
                    int t = t0 + wn * 32 + nf * 8 + (l & 3) * 2;
                    if (t < S) {
                        float2 o;
                        o.x = acc[f][nf][half * 2 + 0] * rq * __ldg(&g_rk[b * S + t]);
                        o.y = acc[f][nf][half * 2 + 1] * rq * __ldg(&g_rk[b * S + t + 1]);
                        *(float2*)(outp + (size_t)s * S + t) = o;
                    }
                }
            }
        }
    }
}

// ---------------------------------------------------------------------------
// K3: split-K reduce + causal softmax -> bf16 probabilities.
// grid B*S, 320 threads.
// ---------------------------------------------------------------------------
__global__ __launch_bounds__(S) void softmax_kernel() {
    int row = blockIdx.x;
    int s = row % S;
    int tid = threadIdx.x;
    __shared__ float red[10];

    float x;
    if (tid <= s) {
        x = 0.f;
        #pragma unroll
        for (int sp = 0; sp < SK; sp++)
            x += g_attp[(size_t)sp * (B * S * S) + (size_t)row * S + tid];
    } else {
        x = -1e30f;
    }
    float m = x;
    #pragma unroll
    for (int o = 16; o; o >>= 1) m = fmaxf(m, __shfl_xor_sync(0xffffffffu, m, o));
    if ((tid & 31) == 0) red[tid >> 5] = m;
    __syncthreads();
    float mall = red[0];
    #pragma unroll
    for (int i = 1; i < 10; i++) mall = fmaxf(mall, red[i]);

    float e = (tid <= s) ? expf(x - mall) : 0.f;
    float ssum = e;
    #pragma unroll
    for (int o = 16; o; o >>= 1) ssum += __shfl_xor_sync(0xffffffffu, ssum, o);
    __syncthreads();
    if ((tid & 31) == 0) red[tid >> 5] = ssum;
    __syncthreads();
    float tot = 0.f;
    #pragma unroll
    for (int i = 0; i < 10; i++) tot += red[i];

    g_attb[(size_t)row * S + tid] = __float2bfloat16(e / tot);
}

// ---------------------------------------------------------------------------
// K4: out = att @ V + residual via mma.sync bf16.  Tile M=64(s) x N=256(d),
// K = t-blocks of 64 (causal: stile+1 blocks).  ldmatrix.trans for V.
// grid (80, 5, B), 256 threads, 80KB dynamic smem.
// ---------------------------------------------------------------------------
#define OU_A0 0
#define OU_A1 8192
#define OU_B0 16384
#define OU_B1 49152
#define OU_SMEM 81920

__global__ __launch_bounds__(256) void out_mma(const float* __restrict__ v,
                                               float* __restrict__ out) {
    extern __shared__ char sm[];
    uint32_t sb = smem_u32(sm);
    int ckp = blockIdx.x, stile = blockIdx.y, b = blockIdx.z;
    int s0 = stile * 64, n0 = ckp * 256;
    int tid = threadIdx.x, l = tid & 31, wid = tid >> 5;
    int wm = wid >> 2, wn = wid & 3;    // warp grid 2 (M: 32 rows) x 4 (N: 64 cols)
    int nblocks = stile + 1;

    const __nv_bfloat16* pb = g_attb + (size_t)b * S * S;
    const __nv_bfloat16* vb = g_vb + (size_t)b * S * D_TOT;

    float acc[2][8][4];
    #pragma unroll
    for (int f = 0; f < 2; f++)
        #pragma unroll
        for (int nf = 0; nf < 8; nf++)
            #pragma unroll
            for (int e = 0; e < 4; e++) acc[f][nf][e] = 0.f;

    const uint32_t AOF[2] = {OU_A0, OU_A1}, BOF[2] = {OU_B0, OU_B1};

    // fill block 0
    {
        #pragma unroll
        for (int j = 0; j < 2; j++) {
            int idx = tid + 256 * j, r = idx >> 3, g = idx & 7;
            cpa16(sb + OU_A0 + r * 128 + ((g ^ (r & 7)) << 4), pb + (size_t)(s0 + r) * S + g * 8);
        }
        #pragma unroll
        for (int j = 0; j < 8; j++) {
            int idx = tid + 256 * j, r = idx >> 5, g = idx & 31;
            cpa16(sb + OU_B0 + r * 512 + ((g ^ (r & 7)) << 4), vb + (size_t)r * D_TOT + n0 + g * 8);
        }
        CP_COMMIT();
    }

    for (int tt = 0; tt < nblocks; tt++) {
        int buf = tt & 1;
        if (tt + 1 < nblocks) {
            int t1 = (tt + 1) * 64;
            uint32_t a_of = AOF[buf ^ 1], b_of = BOF[buf ^ 1];
            #pragma unroll
            for (int j = 0; j < 2; j++) {
                int idx = tid + 256 * j, r = idx >> 3, g = idx & 7;
                cpa16(sb + a_of + r * 128 + ((g ^ (r & 7)) << 4), pb + (size_t)(s0 + r) * S + t1 + g * 8);
            }
            #pragma unroll
            for (int j = 0; j < 8; j++) {
                int idx = tid + 256 * j, r = idx >> 5, g = idx & 31;
                cpa16(sb + b_of + r * 512 + ((g ^ (r & 7)) << 4), vb + (size_t)(t1 + r) * D_TOT + n0 + g * 8);
            }
            CP_COMMIT();
            CP_WAIT1();
        } else {
            CP_WAIT0();
        }
        __syncthreads();
        uint32_t Ab = sb + AOF[buf], Bb = sb + BOF[buf];
        #pragma unroll
        for (int kk = 0; kk < 4; kk++) {
            uint32_t af[2][4], bfr[4][4];
            #pragma unroll
            for (int f = 0; f < 2; f++) {
                int rowA = wm * 32 + f * 16 + (l & 15);
                int g = 2 * kk + (l >> 4);
                ldm4(af[f], Ab + rowA * 128 + ((g ^ (l & 7)) << 4));
            }
            #pragma unroll
            for (int h = 0; h < 4; h++) {
                int rowB = kk * 16 + (l & 15);
                int g = wn * 8 + h * 2 + (l >> 4);
                ldm4t(bfr[h], Bb + rowB * 512 + ((g ^ (rowB & 7)) << 4));
            }
            #pragma unroll
            for (int f = 0; f < 2; f++)
                #pragma unroll
                for (int nf = 0; nf < 8; nf++)
                    mma_bf16(acc[f][nf], af[f], &bfr[nf >> 1][(nf & 1) * 2]);
        }
        __syncthreads();
    }

    // epilogue: residual add (fp32 token_v) + store to original layout
    #pragma unroll
    for (int f = 0; f < 2; f++) {
        #pragma unroll
        for (int half = 0; half < 2; half++) {
            int s = s0 + wm * 32 + f * 16 + (l >> 2) + half * 8;
            #pragma unroll
            for (int nf = 0; nf < 8; nf++) {
                int d = n0 + wn * 64 + nf * 8 + (l & 3) * 2;
                int ck = d >> 6, w = d & 63;
                size_t g = elem_base(b, s, ck) + w;
                float2 vv = *(const float2*)(v + g);
                float2 o;
                o.x = acc[f][nf][half * 2 + 0] + vv.x;
                o.y = acc[f][nf][half * 2 + 1] + vv.y;
                *(float2*)(out + g) = o;
            }
        }
    }
}

// ---------------------------------------------------------------------------
extern "C" void kernel_launch(void* const* d_in, const int* in_sizes, int n_in,
                              void* d_out, int out_size) {
    const float* q = (const float*)d_in[0];
    const float* k = (const float*)d_in[1];
    const float* v = (const float*)d_in[2];
    float* out = (float*)d_out;

    static bool attr_done = false;
    if (!attr_done) {
        cudaFuncSetAttribute(scores_mma, cudaFuncAttributeMaxDynamicSharedMemorySize, SC_SMEM);
        cudaFuncSetAttribute(out_mma, cudaFuncAttributeMaxDynamicSharedMemorySize, OU_SMEM);
        attr_done = true;
    }

    convnorm_kernel<<<dim3(B * S, 3), 256>>>(q, k, v);
    scores_mma<<<dim3(6, SK, B), 256, SC_SMEM>>>();
    softmax_kernel<<<B * S, S>>>();
    out_mma<<<dim3(80, 5, B), 256, OU_SMEM>>>(v, out);
}

// round 8
// speedup vs baseline: 4.3477x; 1.1480x over previous
#include <cuda_runtime.h>
#include <cuda_fp16.h>
#include <math.h>
#include <cstdint>

// Problem constants
#define B 4
#define C 64
#define NA 25
#define H 64
#define W 64
#define S 320        // H*U
#define NCHUNK 320   // chunks of 64 floats along w
#define D_TOT 20480  // feature dim
#define BSTRIDE 6553600
#define CSTRIDE 102400
#define NSTRIDE 4096
#define SK 16                       // split-K for scores
#define KSTEPS (D_TOT / SK / 64)    // 20 K-blocks of 64 per split

typedef unsigned long long u64;

// ---- scratch (device globals; no allocations allowed) ----
__device__ float g_rq[B * S];
__device__ float g_rk[B * S];
__device__ float g_attp[(size_t)SK * B * S * S];   // split-K partial scores (f32)
__device__ __half g_attb[(size_t)B * S * S];       // softmax probs (f16)
__device__ __half g_qb[(size_t)B * S * D_TOT];
__device__ __half g_kb[(size_t)B * S * D_TOT];
__device__ __half g_vb[(size_t)B * S * D_TOT];

// original-layout address of (b, s, chunk ck, w=0)
__device__ __forceinline__ size_t elem_base(int b, int s, int ck) {
    int h = s / 5, uu = s - h * 5;
    int c = ck / 5, vv = ck - c * 5;
    return (size_t)b * BSTRIDE + (size_t)c * CSTRIDE + (size_t)(uu * 5 + vv) * NSTRIDE + (size_t)h * W;
}

// ---- PTX helpers (sm_80-level: valid at virtual target sm_103) ----
__device__ __forceinline__ uint32_t smem_u32(const void* p) {
    uint32_t a;
    asm("{ .reg .u64 t; cvta.to.shared.u64 t, %1; cvt.u32.u64 %0, t; }" : "=r"(a) : "l"(p));
    return a;
}
__device__ __forceinline__ void cpa16(uint32_t dst, const void* src) {
    asm volatile("{ .reg .u64 g; cvta.to.global.u64 g, %1; cp.async.cg.shared.global [%0], [g], 16; }"
                 :: "r"(dst), "l"(src) : "memory");
}
#define CP_COMMIT() asm volatile("cp.async.commit_group;" ::: "memory")
#define CP_WAIT0()  asm volatile("cp.async.wait_group 0;" ::: "memory")
#define CP_WAIT1()  asm volatile("cp.async.wait_group 1;" ::: "memory")

__device__ __forceinline__ void ldm4(uint32_t* r, uint32_t addr) {
    asm volatile("ldmatrix.sync.aligned.m8n8.x4.shared.b16 {%0,%1,%2,%3}, [%4];"
                 : "=r"(r[0]), "=r"(r[1]), "=r"(r[2]), "=r"(r[3]) : "r"(addr));
}
__device__ __forceinline__ void ldm4t(uint32_t* r, uint32_t addr) {
    asm volatile("ldmatrix.sync.aligned.m8n8.x4.trans.shared.b16 {%0,%1,%2,%3}, [%4];"
                 : "=r"(r[0]), "=r"(r[1]), "=r"(r[2]), "=r"(r[3]) : "r"(addr));
}
__device__ __forceinline__ void mma_f16(float* d, const uint32_t* a, const uint32_t* b) {
    asm volatile("mma.sync.aligned.m16n8k16.row.col.f32.f16.f16.f32 "
                 "{%0,%1,%2,%3}, {%4,%5,%6,%7}, {%8,%9}, {%0,%1,%2,%3};"
                 : "+f"(d[0]), "+f"(d[1]), "+f"(d[2]), "+f"(d[3])
                 : "r"(a[0]), "r"(a[1]), "r"(a[2]), "r"(a[3]), "r"(b[0]), "r"(b[1]));
}

// ---------------------------------------------------------------------------
// K1: fused gather + f16 convert (Q, K, V) + row inverse-norms (Q, K).
// grid (B*S, 3), 256 threads.
// ---------------------------------------------------------------------------
__global__ __launch_bounds__(256) void convnorm_kernel(const float* __restrict__ q,
                                                       const float* __restrict__ k,
                                                       const float* __restrict__ v) {
    int row = blockIdx.x;
    int which = blockIdx.y;
    const float* src = (which == 0) ? q : (which == 1) ? k : v;
    __half* dstb = (which == 0) ? g_qb : (which == 1) ? g_kb : g_vb;
    int b = row / S, s = row - b * S;

    uint2* drow = (uint2*)(dstb + (size_t)row * D_TOT);
    float acc = 0.f;
    for (int i = threadIdx.x; i < NCHUNK * 16; i += 256) {
        int ck = i >> 4, f4 = i & 15;
        const float4 x = *(const float4*)(src + elem_base(b, s, ck) + f4 * 4);
        acc += x.x * x.x + x.y * x.y + x.z * x.z + x.w * x.w;
        __half2 p0 = __floats2half2_rn(x.x, x.y);
        __half2 p1 = __floats2half2_rn(x.z, x.w);
        uint2 wv;
        *reinterpret_cast<__half2*>(&wv.x) = p0;
        *reinterpret_cast<__half2*>(&wv.y) = p1;
        drow[i] = wv;
    }
    if (which < 2) {
        __shared__ float red[256];
        red[threadIdx.x] = acc;
        __syncthreads();
        for (int off = 128; off; off >>= 1) {
            if (threadIdx.x < off) red[threadIdx.x] += red[threadIdx.x + off];
            __syncthreads();
        }
        if (threadIdx.x == 0)
            (which ? g_rk : g_rq)[row] = 1.f / fmaxf(sqrtf(red[0]), 1e-12f);
    }
}

// ---------------------------------------------------------------------------
// K2: scores = Q K^T via mma.sync f16.  Tile 128x128, K-blocks of 64,
// split-K=16.  cp.async double buffer, XOR-swizzled smem, causal tile list.
// grid (6 pairs, 16 splits, B), 256 threads, 64KB dynamic smem.
// ---------------------------------------------------------------------------
#define SC_A0 0
#define SC_A1 16384
#define SC_B0 32768
#define SC_B1 49152
#define SC_SMEM 65536

__global__ __launch_bounds__(256) void scores_mma() {
    extern __shared__ char sm[];
    uint32_t sb = smem_u32(sm);
    const int MI[6] = {0, 1, 1, 2, 2, 2};
    const int NJ[6] = {0, 0, 1, 0, 1, 2};
    int pair = blockIdx.x, split = blockIdx.y, b = blockIdx.z;
    int s0 = MI[pair] * 128, t0 = NJ[pair] * 128;
    int tid = threadIdx.x, l = tid & 31, wid = tid >> 5;
    int wm = wid >> 2, wn = wid & 3;    // warp grid 2 (M) x 4 (N)
    int d_base = split * (D_TOT / SK);

    const __half* qrow = g_qb + (size_t)b * S * D_TOT;
    const __half* krow = g_kb + (size_t)b * S * D_TOT;

    float acc[4][4][4];
    #pragma unroll
    for (int f = 0; f < 4; f++)
        #pragma unroll
        for (int nf = 0; nf < 4; nf++)
            #pragma unroll
            for (int e = 0; e < 4; e++) acc[f][nf][e] = 0.f;

    const uint32_t AOF[2] = {SC_A0, SC_A1}, BOF[2] = {SC_B0, SC_B1};

    // fill step 0
    {
        int d0 = d_base;
        #pragma unroll
        for (int j = 0; j < 4; j++) {
            int idx = tid + 256 * j, r = idx >> 3, g = idx & 7;
            int s = s0 + r; if (s >= S) s = S - 1;
            cpa16(sb + SC_A0 + r * 128 + ((g ^ (r & 7)) << 4), qrow + (size_t)s * D_TOT + d0 + g * 8);
        }
        #pragma unroll
        for (int j = 0; j < 4; j++) {
            int idx = tid + 256 * j, r = idx >> 3, g = idx & 7;
            int t = t0 + r; if (t >= S) t = S - 1;
            cpa16(sb + SC_B0 + r * 128 + ((g ^ (r & 7)) << 4), krow + (size_t)t * D_TOT + d0 + g * 8);
        }
        CP_COMMIT();
    }

    for (int step = 0; step < KSTEPS; step++) {
        int buf = step & 1;
        if (step + 1 < KSTEPS) {
            int d0 = d_base + (step + 1) * 64;
            uint32_t a_of = AOF[buf ^ 1], b_of = BOF[buf ^ 1];
            #pragma unroll
            for (int j = 0; j < 4; j++) {
                int idx = tid + 256 * j, r = idx >> 3, g = idx & 7;
                int s = s0 + r; if (s >= S) s = S - 1;
                cpa16(sb + a_of + r * 128 + ((g ^ (r & 7)) << 4), qrow + (size_t)s * D_TOT + d0 + g * 8);
            }
            #pragma unroll
            for (int j = 0; j < 4; j++) {
                int idx = tid + 256 * j, r = idx >> 3, g = idx & 7;
                int t = t0 + r; if (t >= S) t = S - 1;
                cpa16(sb + b_of + r * 128 + ((g ^ (r & 7)) << 4), krow + (size_t)t * D_TOT + d0 + g * 8);
            }
            CP_COMMIT();
            CP_WAIT1();
        } else {
            CP_WAIT0();
        }
        __syncthreads();
        uint32_t Ab = sb + AOF[buf], Bb = sb + BOF[buf];
        #pragma unroll
        for (int kk = 0; kk < 4; kk++) {
            uint32_t af[4][4], bfr[2][4];
            #pragma unroll
            for (int f = 0; f < 4; f++) {
                int rowA = wm * 64 + f * 16 + (l & 15);
                int g = 2 * kk + (l >> 4);
                ldm4(af[f], Ab + rowA * 128 + ((g ^ (l & 7)) << 4));
            }
            #pragma unroll
            for (int h = 0; h < 2; h++) {
                int rowB = wn * 32 + h * 16 + (l & 7) + ((l >> 4) << 3);
                int g = 2 * kk + ((l >> 3) & 1);
                ldm4(bfr[h], Bb + rowB * 128 + ((g ^ (rowB & 7)) << 4));
            }
            #pragma unroll
            for (int f = 0; f < 4; f++)
                #pragma unroll
                for (int nf = 0; nf < 4; nf++)
                    mma_f16(acc[f][nf], af[f], &bfr[nf >> 1][(nf & 1) * 2]);
        }
        __syncthreads();
    }

    // epilogue: apply rq*rk, store split partials
    float* outp = g_attp + (size_t)split * (B * S * S) + (size_t)b * S * S;
    #pragma unroll
    for (int f = 0; f < 4; f++) {
        int r0 = s0 + wm * 64 + f * 16 + (l >> 2);
        #pragma unroll
        for (int half = 0; half < 2; half++) {
            int s = r0 + half * 8;
            if (s < S) {
                float rq = __ldg(&g_rq[b * S + s]);
                #pragma unroll
                for (int nf = 0; nf < 4; nf++) {
                    int t = t0 + wn * 32 + nf * 8 + (l & 3) * 2;
                    if (t < S) {
                        float2 o;
                        o.x = acc[f][nf][half * 2 + 0] * rq * __ldg(&g_rk[b * S + t]);
                        o.y = acc[f][nf][half * 2 + 1] * rq * __ldg(&g_rk[b * S + t + 1]);
                        *(float2*)(outp + (size_t)s * S + t) = o;
                    }
                }
            }
        }
    }
}

// ---------------------------------------------------------------------------
// K3: split-K reduce + causal softmax -> f16 probabilities.
// grid B*S, 320 threads.
// ---------------------------------------------------------------------------
__global__ __launch_bounds__(S) void softmax_kernel() {
    int row = blockIdx.x;
    int s = row % S;
    int tid = threadIdx.x;
    __shared__ float red[10];

    float x;
    if (tid <= s) {
        x = 0.f;
        #pragma unroll
        for (int sp = 0; sp < SK; sp++)
            x += g_attp[(size_t)sp * (B * S * S) + (size_t)row * S + tid];
    } else {
        x = -1e30f;
    }
    float m = x;
    #pragma unroll
    for (int o = 16; o; o >>= 1) m = fmaxf(m, __shfl_xor_sync(0xffffffffu, m, o));
    if ((tid & 31) == 0) red[tid >> 5] = m;
    __syncthreads();
    float mall = red[0];
    #pragma unroll
    for (int i = 1; i < 10; i++) mall = fmaxf(mall, red[i]);

    float e = (tid <= s) ? expf(x - mall) : 0.f;
    float ssum = e;
    #pragma unroll
    for (int o = 16; o; o >>= 1) ssum += __shfl_xor_sync(0xffffffffu, ssum, o);
    __syncthreads();
    if ((tid & 31) == 0) red[tid >> 5] = ssum;
    __syncthreads();
    float tot = 0.f;
    #pragma unroll
    for (int i = 0; i < 10; i++) tot += red[i];

    g_attb[(size_t)row * S + tid] = __float2half(e / tot);
}

// ---------------------------------------------------------------------------
// K4: out = att @ V + residual via mma.sync f16.  Tile M=64(s) x N=128(d),
// K = t-blocks of 64 (causal: stile+1 blocks).  48KB smem -> 4 CTAs/SM.
// grid (160, 5, B), 256 threads.
// ---------------------------------------------------------------------------
#define OU_A0 0
#define OU_A1 8192
#define OU_B0 16384
#define OU_B1 32768
#define OU_SMEM 49152

__global__ __launch_bounds__(256) void out_mma(const float* __restrict__ v,
                                               float* __restrict__ out) {
    extern __shared__ char sm[];
    uint32_t sb = smem_u32(sm);
    int ckp = blockIdx.x, stile = blockIdx.y, b = blockIdx.z;
    int s0 = stile * 64, n0 = ckp * 128;
    int tid = threadIdx.x, l = tid & 31, wid = tid >> 5;
    int wm = wid >> 2, wn = wid & 3;    // warp grid 2 (M: 32 rows) x 4 (N: 32 cols)
    int nblocks = stile + 1;

    const __half* pb = g_attb + (size_t)b * S * S;
    const __half* vb = g_vb + (size_t)b * S * D_TOT;

    float acc[2][4][4];
    #pragma unroll
    for (int f = 0; f < 2; f++)
        #pragma unroll
        for (int nf = 0; nf < 4; nf++)
            #pragma unroll
            for (int e = 0; e < 4; e++) acc[f][nf][e] = 0.f;

    const uint32_t AOF[2] = {OU_A0, OU_A1}, BOF[2] = {OU_B0, OU_B1};

    // fill block 0: A = att tile 64x64 (128B rows), B = V tile 64x128 (256B rows)
    {
        #pragma unroll
        for (int j = 0; j < 2; j++) {
            int idx = tid + 256 * j, r = idx >> 3, g = idx & 7;
            cpa16(sb + OU_A0 + r * 128 + ((g ^ (r & 7)) << 4), pb + (size_t)(s0 + r) * S + g * 8);
        }
        #pragma unroll
        for (int j = 0; j < 4; j++) {
            int idx = tid + 256 * j, r = idx >> 4, g = idx & 15;
            cpa16(sb + OU_B0 + r * 256 + ((g ^ (r & 7)) << 4), vb + (size_t)r * D_TOT + n0 + g * 8);
        }
        CP_COMMIT();
    }

    for (int tt = 0; tt < nblocks; tt++) {
        int buf = tt & 1;
        if (tt + 1 < nblocks) {
            int t1 = (tt + 1) * 64;
            uint32_t a_of = AOF[buf ^ 1], b_of = BOF[buf ^ 1];
            #pragma unroll
            for (int j = 0; j < 2; j++) {
                int idx = tid + 256 * j, r = idx >> 3, g = idx & 7;
                cpa16(sb + a_of + r * 128 + ((g ^ (r & 7)) << 4), pb + (size_t)(s0 + r) * S + t1 + g * 8);
            }
            #pragma unroll
            for (int j = 0; j < 4; j++) {
                int idx = tid + 256 * j, r = idx >> 4, g = idx & 15;
                cpa16(sb + b_of + r * 256 + ((g ^ (r & 7)) << 4), vb + (size_t)(t1 + r) * D_TOT + n0 + g * 8);
            }
            CP_COMMIT();
            CP_WAIT1();
        } else {
            CP_WAIT0();
        }
        __syncthreads();
        uint32_t Ab = sb + AOF[buf], Bb = sb + BOF[buf];
        #pragma unroll
        for (int kk = 0; kk < 4; kk++) {
            uint32_t af[2][4], bfr[2][4];
            #pragma unroll
            for (int f = 0; f < 2; f++) {
                int rowA = wm * 32 + f * 16 + (l & 15);
                int g = 2 * kk + (l >> 4);
                ldm4(af[f], Ab + rowA * 128 + ((g ^ (l & 7)) << 4));
            }
            #pragma unroll
            for (int h = 0; h < 2; h++) {
                int rowB = kk * 16 + (l & 15);
                int g = wn * 4 + h * 2 + (l >> 4);
                ldm4t(bfr[h], Bb + rowB * 256 + ((g ^ (rowB & 7)) << 4));
            }
            #pragma unroll
            for (int f = 0; f < 2; f++)
                #pragma unroll
                for (int nf = 0; nf < 4; nf++)
                    mma_f16(acc[f][nf], af[f], &bfr[nf >> 1][(nf & 1) * 2]);
        }
        __syncthreads();
    }

    // epilogue: residual add (fp32 token_v) + store to original layout
    #pragma unroll
    for (int f = 0; f < 2; f++) {
        #pragma unroll
        for (int half = 0; half < 2; half++) {
            int s = s0 + wm * 32 + f * 16 + (l >> 2) + half * 8;
            #pragma unroll
            for (int nf = 0; nf < 4; nf++) {
                int d = n0 + wn * 32 + nf * 8 + (l & 3) * 2;
                int ck = d >> 6, w = d & 63;
                size_t g = elem_base(b, s, ck) + w;
                float2 vv = *(const float2*)(v + g);
                float2 o;
                o.x = acc[f][nf][half * 2 + 0] + vv.x;
                o.y = acc[f][nf][half * 2 + 1] + vv.y;
                *(float2*)(out + g) = o;
            }
        }
    }
}

// ---------------------------------------------------------------------------
extern "C" void kernel_launch(void* const* d_in, const int* in_sizes, int n_in,
                              void* d_out, int out_size) {
    const float* q = (const float*)d_in[0];
    const float* k = (const float*)d_in[1];
    const float* v = (const float*)d_in[2];
    float* out = (float*)d_out;

    static bool attr_done = false;
    if (!attr_done) {
        cudaFuncSetAttribute(scores_mma, cudaFuncAttributeMaxDynamicSharedMemorySize, SC_SMEM);
        cudaFuncSetAttribute(out_mma, cudaFuncAttributeMaxDynamicSharedMemorySize, OU_SMEM);
        attr_done = true;
    }

    convnorm_kernel<<<dim3(B * S, 3), 256>>>(q, k, v);
    scores_mma<<<dim3(6, SK, B), 256, SC_SMEM>>>();
    softmax_kernel<<<B * S, S>>>();
    out_mma<<<dim3(160, 5, B), 256, OU_SMEM>>>(v, out);
}